// round 9
// baseline (speedup 1.0000x reference)
#include <cuda_runtime.h>
#include <cuda_bf16.h>
#include <cstdint>

// Problem constants
#define NWIN   1024           // 16 batches * 8 * 8 windows
#define MTOT   65536          // NWIN * 64 tokens
#define CDIM   512
#define QKVN   1536

// Scratch (device globals — no allocation allowed)
__device__ __nv_bfloat16 g_xw_hi[(size_t)MTOT * CDIM];
__device__ __nv_bfloat16 g_xw_lo[(size_t)MTOT * CDIM];
__device__ float         g_qkv  [(size_t)3 * MTOT * CDIM];   // [s][w][h][t][d]
__device__ __nv_bfloat16 g_xo_hi[(size_t)MTOT * CDIM];
__device__ __nv_bfloat16 g_xo_lo[(size_t)MTOT * CDIM];
__device__ __nv_bfloat16 g_wq_hi[(size_t)QKVN * CDIM];
__device__ __nv_bfloat16 g_wq_lo[(size_t)QKVN * CDIM];
__device__ __nv_bfloat16 g_wp_hi[(size_t)CDIM * CDIM];
__device__ __nv_bfloat16 g_wp_lo[(size_t)CDIM * CDIM];

// ---------------------------------------------------------------------------
// helpers (all plain sm_80-era PTX — valid on compute_103 base target)
// ---------------------------------------------------------------------------
__device__ __forceinline__ uint32_t smem_u32(const void* p) {
    uint32_t a;
    asm("{ .reg .u64 t; cvta.to.shared.u64 t, %1; cvt.u32.u64 %0, t; }" : "=r"(a) : "l"(p));
    return a;
}
__device__ __forceinline__ void cp16(uint32_t s, const void* g) {
    asm volatile("cp.async.cg.shared.global [%0], [%1], 16;" :: "r"(s), "l"(g));
}
__device__ __forceinline__ void ldm_x4(uint32_t* r, uint32_t addr) {
    asm volatile("ldmatrix.sync.aligned.m8n8.x4.shared.b16 {%0,%1,%2,%3}, [%4];"
                 : "=r"(r[0]), "=r"(r[1]), "=r"(r[2]), "=r"(r[3]) : "r"(addr));
}
__device__ __forceinline__ void mma16816(float* c, const uint32_t* a, const uint32_t* b) {
    asm volatile(
        "mma.sync.aligned.m16n8k16.row.col.f32.bf16.bf16.f32 "
        "{%0,%1,%2,%3}, {%4,%5,%6,%7}, {%8,%9}, {%0,%1,%2,%3};"
        : "+f"(c[0]), "+f"(c[1]), "+f"(c[2]), "+f"(c[3])
        : "r"(a[0]), "r"(a[1]), "r"(a[2]), "r"(a[3]), "r"(b[0]), "r"(b[1]));
}

// ---------------------------------------------------------------------------
// 1) Gather + bf16 split: xw[w, t, cc] = x[b, n(i,j), c]
//    c = (t&7)*64 + (t>>3)*8 + cc/64 ; i = (cc>>3)&7 ; j = cc&7
// ---------------------------------------------------------------------------
__global__ __launch_bounds__(256) void gather_split_kernel(const float* __restrict__ x) {
    int idx = blockIdx.x * blockDim.x + threadIdx.x;      // [0, NWIN*64*64)
    int cc64 = idx & 63;
    int t    = (idx >> 6) & 63;
    int w    = idx >> 12;
    int b  = w >> 6;
    int wh = (w >> 3) & 7;
    int ww = w & 7;
    int i = cc64 >> 3;
    int j = cc64 & 7;
    int base_c = (t & 7) * 64 + (t >> 3) * 8;
    int n = (wh * 8 + i) * 64 + (ww * 8 + j);
    const float* src = x + ((size_t)(b * 4096 + n)) * 512 + base_c;
    float4 v0 = *(const float4*)(src);
    float4 v1 = *(const float4*)(src + 4);
    float vv[8] = {v0.x, v0.y, v0.z, v0.w, v1.x, v1.y, v1.z, v1.w};
    size_t off = (size_t)w * 32768 + t * 512 + cc64;
#pragma unroll
    for (int r = 0; r < 8; r++) {
        float v = vv[r];
        __nv_bfloat16 h = __float2bfloat16(v);
        g_xw_hi[off + 64 * r] = h;
        g_xw_lo[off + 64 * r] = __float2bfloat16(v - __bfloat162float(h));
    }
}

// ---------------------------------------------------------------------------
// 1b) Weight split (w_qkv 1536x512, w_proj 512x512)
// ---------------------------------------------------------------------------
__global__ __launch_bounds__(256) void wsplit_kernel(const float* __restrict__ wq,
                                                     const float* __restrict__ wp) {
    int i = blockIdx.x * blockDim.x + threadIdx.x;
    if (i < QKVN * CDIM) {
        float v = wq[i];
        __nv_bfloat16 h = __float2bfloat16(v);
        g_wq_hi[i] = h;
        g_wq_lo[i] = __float2bfloat16(v - __bfloat162float(h));
    } else {
        int k = i - QKVN * CDIM;
        float v = wp[k];
        __nv_bfloat16 h = __float2bfloat16(v);
        g_wp_hi[k] = h;
        g_wp_lo[k] = __float2bfloat16(v - __bfloat162float(h));
    }
}

// ---------------------------------------------------------------------------
// 2) bf16x3 HMMA GEMM: D[m,n] = sum_k A[m,k]*B[n,k], 3 hi/lo passes summed in
//    fp32 register accumulators (err ~2^-16 relative — well under 1e-3).
//    CTA tile 128x128, 8 warps (2x4), warp tile 64x32, K-chunk 64 (128B rows,
//    XOR-16B swizzle -> conflict-free ldmatrix). 3-stage cp.async pipeline.
//    mode 0: A=g_xw, B=g_wq, epilogue scatter to g_qkv[s][w][h][t][d]
//    mode 1: A=g_xo, B=g_wp, epilogue bias + window-merge to out
// ---------------------------------------------------------------------------
#define STG   32768                  // A(16KB) + B(16KB) per stage
#define GSMEM (3 * STG + 1024)
#define NITER 24                     // 3 passes * 8 k-chunks

extern "C" __global__ __launch_bounds__(256, 2)
void gemm3_kernel(const float* __restrict__ bias, float* __restrict__ outp, int mode) {
    extern __shared__ char smem[];
    const int tid  = threadIdx.x;
    const int lane = tid & 31;
    const int wid  = tid >> 5;
    const int wm   = wid & 1;            // 2 warp rows   (64 m each)
    const int wn   = wid >> 1;           // 4 warp cols   (32 n each)
    const int m0 = blockIdx.x * 128;
    const int n0 = blockIdx.y * 128;

    const __nv_bfloat16* Ahi = (mode == 0) ? g_xw_hi : g_xo_hi;
    const __nv_bfloat16* Alo = (mode == 0) ? g_xw_lo : g_xo_lo;
    const __nv_bfloat16* Bhi = (mode == 0) ? g_wq_hi : g_wp_hi;
    const __nv_bfloat16* Blo = (mode == 0) ? g_wq_lo : g_wp_lo;

    uint32_t sbase = smem_u32(smem);
    uint32_t tile0 = (sbase + 1023) & ~1023u;

    float acc[4][4][4];
#pragma unroll
    for (int a = 0; a < 4; a++)
#pragma unroll
        for (int b = 0; b < 4; b++)
#pragma unroll
            for (int c = 0; c < 4; c++) acc[a][b][c] = 0.f;

    // ---- stage loader: one K-chunk (64) of A(128 rows) + B(128 rows) ----
    auto load_stage = [&](int st, int it) {
        int pass = it >> 3;                  // 0: hi*hi, 1: lo*hi, 2: hi*lo
        int kb   = (it & 7) << 6;
        const __nv_bfloat16* Ap = (pass == 1) ? Alo : Ahi;
        const __nv_bfloat16* Bp = (pass == 2) ? Blo : Bhi;
        uint32_t sa = tile0 + st * STG;
        uint32_t sb = sa + 16384;
#pragma unroll
        for (int v = 0; v < 4; v++) {
            int c = tid + v * 256;           // 0..1023
            int r = c >> 3, g = c & 7;
            uint32_t so = r * 128 + ((g ^ (r & 7)) << 4);
            cp16(sa + so, Ap + (size_t)(m0 + r) * 512 + kb + g * 8);
            cp16(sb + so, Bp + (size_t)(n0 + r) * 512 + kb + g * 8);
        }
        asm volatile("cp.async.commit_group;" ::: "memory");
    };

    load_stage(0, 0);
    load_stage(1, 1);

    const int la = lane & 15;                // ldmatrix row within 16
    const int hi = lane >> 4;                // 0: k-lo 16B, 1: k-hi 16B

    for (int it = 0; it < NITER; ++it) {
        asm volatile("cp.async.wait_group 1;" ::: "memory");
        __syncthreads();
        if (it + 2 < NITER) load_stage((it + 2) % 3, it + 2);
        else asm volatile("cp.async.commit_group;" ::: "memory");   // keep group count aligned

        uint32_t sa = tile0 + (it % 3) * STG;
        uint32_t sb = sa + 16384;
#pragma unroll
        for (int s = 0; s < 4; s++) {        // 4 x k16 within the 64-chunk
            uint32_t af[4][4];
#pragma unroll
            for (int mt = 0; mt < 4; mt++) {
                int r  = wm * 64 + mt * 16 + la;
                int ch = 2 * s + hi;
                ldm_x4(af[mt], sa + r * 128 + ((ch ^ (r & 7)) << 4));
            }
            uint32_t bf[4][2];
#pragma unroll
            for (int nh = 0; nh < 2; nh++) {
                int r  = wn * 32 + nh * 16 + la;
                int ch = 2 * s + hi;
                uint32_t t4[4];
                ldm_x4(t4, sb + r * 128 + ((ch ^ (r & 7)) << 4));
                bf[nh * 2 + 0][0] = t4[0]; bf[nh * 2 + 0][1] = t4[2];
                bf[nh * 2 + 1][0] = t4[1]; bf[nh * 2 + 1][1] = t4[3];
            }
#pragma unroll
            for (int mt = 0; mt < 4; mt++)
#pragma unroll
                for (int nt = 0; nt < 4; nt++)
                    mma16816(acc[mt][nt], af[mt], bf[nt]);
        }
        __syncthreads();
    }

    // ---- epilogue straight from C fragments ----
    const int row0 = lane >> 2;              // 0..7
    const int col0 = (lane & 3) * 2;         // 0,2,4,6
#pragma unroll
    for (int mt = 0; mt < 4; mt++) {
#pragma unroll
        for (int half = 0; half < 2; half++) {
            int m = m0 + wm * 64 + mt * 16 + row0 + half * 8;
            int w = m >> 6, tt = m & 63;
#pragma unroll
            for (int nt = 0; nt < 4; nt++) {
                int n = n0 + wn * 32 + nt * 8 + col0;
                float v0 = acc[mt][nt][half * 2 + 0];
                float v1 = acc[mt][nt][half * 2 + 1];
                if (mode == 0) {
                    int s = n >> 9, h = (n >> 5) & 15, d = n & 31;
                    float* dst = g_qkv + (((size_t)s * NWIN + w) * 16 + h) * 2048
                               + (size_t)tt * 32 + d;
                    *(float2*)dst = make_float2(v0, v1);
                } else {
                    int b  = w >> 6;
                    int wh = (w >> 3) & 7;
                    int ww = w & 7;
                    int p = tt >> 3, q = tt & 7;
                    int npos = (wh * 8 + p) * 64 + (ww * 8 + q);
                    float2 bi = *(const float2*)(bias + n);
                    float* dst = outp + ((size_t)(b * 4096 + npos)) * 512 + n;
                    *(float2*)dst = make_float2(v0 + bi.x, v1 + bi.y);
                }
            }
        }
    }
}

// ---------------------------------------------------------------------------
// 3) Attention v2: 128 threads = 2 (window,head) pairs per block; one thread
//    per query row. Q lives in registers; K/V read from smem as float4
//    (LDS:FMA = 1:4 instead of 1:1). Epilogue emits bf16 hi/lo for proj GEMM.
// ---------------------------------------------------------------------------
__global__ __launch_bounds__(128) void attn_kernel() {
    __shared__ float Ks[2][64 * 32];
    __shared__ float Vs[2][64 * 32];
    const int quad = threadIdx.x >> 6;            // 0..1
    const int t    = threadIdx.x & 63;            // query row
    const int gi = blockIdx.x * 2 + quad;
    const int w = gi >> 4;
    const int h = gi & 15;
    const size_t base = ((size_t)w * 16 + h) * 2048;
    const float* qb = g_qkv + base;
    const float* kb = g_qkv + (size_t)MTOT * 512 + base;
    const float* vb = g_qkv + (size_t)2 * MTOT * 512 + base;

    // K/V tile -> smem (512 float4 per pair, 64 threads -> 8 each)
#pragma unroll
    for (int v = 0; v < 8; v++) {
        int idx = v * 64 + t;
        ((float4*)Ks[quad])[idx] = ((const float4*)kb)[idx];
        ((float4*)Vs[quad])[idx] = ((const float4*)vb)[idx];
    }
    // Q row -> registers
    float4 q[8];
#pragma unroll
    for (int d = 0; d < 8; d++) q[d] = ((const float4*)qb)[t * 8 + d];
    __syncthreads();

    float s[64];
    float mx = -1e30f;
#pragma unroll
    for (int tt = 0; tt < 64; tt++) {
        const float4* kk = (const float4*)(Ks[quad] + tt * 32);  // broadcast per warp
        float dot = 0.f;
#pragma unroll
        for (int d = 0; d < 8; d++) {
            float4 kv = kk[d];
            dot += q[d].x * kv.x + q[d].y * kv.y + q[d].z * kv.z + q[d].w * kv.w;
        }
        dot *= 0.17677669529663687f;              // 1/sqrt(32)
        s[tt] = dot;
        mx = fmaxf(mx, dot);
    }
    float sum = 0.f;
#pragma unroll
    for (int tt = 0; tt < 64; tt++) {
        float e = __expf(s[tt] - mx);
        s[tt] = e;
        sum += e;
    }
    float4 o[8];
#pragma unroll
    for (int d = 0; d < 8; d++) o[d] = make_float4(0.f, 0.f, 0.f, 0.f);
#pragma unroll
    for (int tt = 0; tt < 64; tt++) {
        float p = s[tt];
        const float4* vv = (const float4*)(Vs[quad] + tt * 32);
#pragma unroll
        for (int d = 0; d < 8; d++) {
            float4 vvv = vv[d];
            o[d].x += p * vvv.x; o[d].y += p * vvv.y;
            o[d].z += p * vvv.z; o[d].w += p * vvv.w;
        }
    }
    const float inv = 1.f / sum;
    size_t ob = ((size_t)w * 64 + t) * 512 + h * 32;
#pragma unroll
    for (int d = 0; d < 8; d++) {
        float v4[4] = {o[d].x * inv, o[d].y * inv, o[d].z * inv, o[d].w * inv};
        __nv_bfloat16 hb[4], lb[4];
#pragma unroll
        for (int jj = 0; jj < 4; jj++) {
            __nv_bfloat16 hh = __float2bfloat16(v4[jj]);
            hb[jj] = hh;
            lb[jj] = __float2bfloat16(v4[jj] - __bfloat162float(hh));
        }
        *(uint2*)(g_xo_hi + ob + d * 4) = *(uint2*)hb;
        *(uint2*)(g_xo_lo + ob + d * 4) = *(uint2*)lb;
    }
}

// ---------------------------------------------------------------------------
extern "C" void kernel_launch(void* const* d_in, const int* in_sizes, int n_in,
                              void* d_out, int out_size) {
    const float* x      = (const float*)d_in[0];
    const float* w_qkv  = (const float*)d_in[1];
    const float* w_proj = (const float*)d_in[2];
    const float* b_proj = (const float*)d_in[3];
    float* out = (float*)d_out;

    cudaFuncSetAttribute(gemm3_kernel, cudaFuncAttributeMaxDynamicSharedMemorySize, GSMEM);

    gather_split_kernel<<<16384, 256>>>(x);
    wsplit_kernel<<<4096, 256>>>(w_qkv, w_proj);
    gemm3_kernel<<<dim3(512, 12), 256, GSMEM>>>(nullptr, nullptr, 0);  // QKV
    attn_kernel<<<8192, 128>>>();                                      // 2 pairs/block
    gemm3_kernel<<<dim3(512, 4), 256, GSMEM>>>(b_proj, out, 1);        // proj
}

// round 10
// speedup vs baseline: 1.1871x; 1.1871x over previous
#include <cuda_runtime.h>
#include <cuda_bf16.h>
#include <cstdint>

// Problem constants
#define NWIN   1024           // 16 batches * 8 * 8 windows
#define MTOT   65536          // NWIN * 64 tokens
#define CDIM   512
#define QKVN   1536

// Scratch (device globals — no allocation allowed)
__device__ __nv_bfloat16 g_xw_hi[(size_t)MTOT * CDIM];
__device__ __nv_bfloat16 g_xw_lo[(size_t)MTOT * CDIM];
__device__ float         g_qkv  [(size_t)3 * MTOT * CDIM];   // [s][w][h][t][d]
__device__ __nv_bfloat16 g_xo_hi[(size_t)MTOT * CDIM];
__device__ __nv_bfloat16 g_xo_lo[(size_t)MTOT * CDIM];
__device__ __nv_bfloat16 g_wq_hi[(size_t)QKVN * CDIM];
__device__ __nv_bfloat16 g_wq_lo[(size_t)QKVN * CDIM];
__device__ __nv_bfloat16 g_wp_hi[(size_t)CDIM * CDIM];
__device__ __nv_bfloat16 g_wp_lo[(size_t)CDIM * CDIM];

// ---------------------------------------------------------------------------
// helpers (all plain sm_80-era PTX — valid on compute_103 base target)
// ---------------------------------------------------------------------------
__device__ __forceinline__ uint32_t smem_u32(const void* p) {
    uint32_t a;
    asm("{ .reg .u64 t; cvta.to.shared.u64 t, %1; cvt.u32.u64 %0, t; }" : "=r"(a) : "l"(p));
    return a;
}
__device__ __forceinline__ void cp16(uint32_t s, const void* g) {
    asm volatile("cp.async.cg.shared.global [%0], [%1], 16;" :: "r"(s), "l"(g));
}
__device__ __forceinline__ void ldm_x4(uint32_t* r, uint32_t addr) {
    asm volatile("ldmatrix.sync.aligned.m8n8.x4.shared.b16 {%0,%1,%2,%3}, [%4];"
                 : "=r"(r[0]), "=r"(r[1]), "=r"(r[2]), "=r"(r[3]) : "r"(addr));
}
__device__ __forceinline__ void ldm_x4_t(uint32_t* r, uint32_t addr) {
    asm volatile("ldmatrix.sync.aligned.m8n8.x4.trans.shared.b16 {%0,%1,%2,%3}, [%4];"
                 : "=r"(r[0]), "=r"(r[1]), "=r"(r[2]), "=r"(r[3]) : "r"(addr));
}
__device__ __forceinline__ void mma16816(float* c, const uint32_t* a, const uint32_t* b) {
    asm volatile(
        "mma.sync.aligned.m16n8k16.row.col.f32.bf16.bf16.f32 "
        "{%0,%1,%2,%3}, {%4,%5,%6,%7}, {%8,%9}, {%0,%1,%2,%3};"
        : "+f"(c[0]), "+f"(c[1]), "+f"(c[2]), "+f"(c[3])
        : "r"(a[0]), "r"(a[1]), "r"(a[2]), "r"(a[3]), "r"(b[0]), "r"(b[1]));
}
__device__ __forceinline__ uint32_t packbf(__nv_bfloat16 a, __nv_bfloat16 b) {
    uint32_t lo = *(uint16_t*)&a, hi = *(uint16_t*)&b;
    return lo | (hi << 16);
}

// ---------------------------------------------------------------------------
// 1) Gather + bf16 split: xw[w, t, cc] = x[b, n(i,j), c]
// ---------------------------------------------------------------------------
__global__ __launch_bounds__(256) void gather_split_kernel(const float* __restrict__ x) {
    int idx = blockIdx.x * blockDim.x + threadIdx.x;      // [0, NWIN*64*64)
    int cc64 = idx & 63;
    int t    = (idx >> 6) & 63;
    int w    = idx >> 12;
    int b  = w >> 6;
    int wh = (w >> 3) & 7;
    int ww = w & 7;
    int i = cc64 >> 3;
    int j = cc64 & 7;
    int base_c = (t & 7) * 64 + (t >> 3) * 8;
    int n = (wh * 8 + i) * 64 + (ww * 8 + j);
    const float* src = x + ((size_t)(b * 4096 + n)) * 512 + base_c;
    float4 v0 = *(const float4*)(src);
    float4 v1 = *(const float4*)(src + 4);
    float vv[8] = {v0.x, v0.y, v0.z, v0.w, v1.x, v1.y, v1.z, v1.w};
    size_t off = (size_t)w * 32768 + t * 512 + cc64;
#pragma unroll
    for (int r = 0; r < 8; r++) {
        float v = vv[r];
        __nv_bfloat16 h = __float2bfloat16(v);
        g_xw_hi[off + 64 * r] = h;
        g_xw_lo[off + 64 * r] = __float2bfloat16(v - __bfloat162float(h));
    }
}

// ---------------------------------------------------------------------------
// 1b) Weight split (w_qkv 1536x512, w_proj 512x512)
// ---------------------------------------------------------------------------
__global__ __launch_bounds__(256) void wsplit_kernel(const float* __restrict__ wq,
                                                     const float* __restrict__ wp) {
    int i = blockIdx.x * blockDim.x + threadIdx.x;
    if (i < QKVN * CDIM) {
        float v = wq[i];
        __nv_bfloat16 h = __float2bfloat16(v);
        g_wq_hi[i] = h;
        g_wq_lo[i] = __float2bfloat16(v - __bfloat162float(h));
    } else {
        int k = i - QKVN * CDIM;
        float v = wp[k];
        __nv_bfloat16 h = __float2bfloat16(v);
        g_wp_hi[k] = h;
        g_wp_lo[k] = __float2bfloat16(v - __bfloat162float(h));
    }
}

// ---------------------------------------------------------------------------
// 2) bf16x3 HMMA GEMM (unchanged from the 1500us baseline)
// ---------------------------------------------------------------------------
#define STG   32768                  // A(16KB) + B(16KB) per stage
#define GSMEM (3 * STG + 1024)
#define NITER 24                     // 3 passes * 8 k-chunks

extern "C" __global__ __launch_bounds__(256, 2)
void gemm3_kernel(const float* __restrict__ bias, float* __restrict__ outp, int mode) {
    extern __shared__ char smem[];
    const int tid  = threadIdx.x;
    const int lane = tid & 31;
    const int wid  = tid >> 5;
    const int wm   = wid & 1;
    const int wn   = wid >> 1;
    const int m0 = blockIdx.x * 128;
    const int n0 = blockIdx.y * 128;

    const __nv_bfloat16* Ahi = (mode == 0) ? g_xw_hi : g_xo_hi;
    const __nv_bfloat16* Alo = (mode == 0) ? g_xw_lo : g_xo_lo;
    const __nv_bfloat16* Bhi = (mode == 0) ? g_wq_hi : g_wp_hi;
    const __nv_bfloat16* Blo = (mode == 0) ? g_wq_lo : g_wp_lo;

    uint32_t sbase = smem_u32(smem);
    uint32_t tile0 = (sbase + 1023) & ~1023u;

    float acc[4][4][4];
#pragma unroll
    for (int a = 0; a < 4; a++)
#pragma unroll
        for (int b = 0; b < 4; b++)
#pragma unroll
            for (int c = 0; c < 4; c++) acc[a][b][c] = 0.f;

    auto load_stage = [&](int st, int it) {
        int pass = it >> 3;
        int kb   = (it & 7) << 6;
        const __nv_bfloat16* Ap = (pass == 1) ? Alo : Ahi;
        const __nv_bfloat16* Bp = (pass == 2) ? Blo : Bhi;
        uint32_t sa = tile0 + st * STG;
        uint32_t sb = sa + 16384;
#pragma unroll
        for (int v = 0; v < 4; v++) {
            int c = tid + v * 256;
            int r = c >> 3, g = c & 7;
            uint32_t so = r * 128 + ((g ^ (r & 7)) << 4);
            cp16(sa + so, Ap + (size_t)(m0 + r) * 512 + kb + g * 8);
            cp16(sb + so, Bp + (size_t)(n0 + r) * 512 + kb + g * 8);
        }
        asm volatile("cp.async.commit_group;" ::: "memory");
    };

    load_stage(0, 0);
    load_stage(1, 1);

    const int la = lane & 15;
    const int hi = lane >> 4;

    for (int it = 0; it < NITER; ++it) {
        asm volatile("cp.async.wait_group 1;" ::: "memory");
        __syncthreads();
        if (it + 2 < NITER) load_stage((it + 2) % 3, it + 2);
        else asm volatile("cp.async.commit_group;" ::: "memory");

        uint32_t sa = tile0 + (it % 3) * STG;
        uint32_t sb = sa + 16384;
#pragma unroll
        for (int s = 0; s < 4; s++) {
            uint32_t af[4][4];
#pragma unroll
            for (int mt = 0; mt < 4; mt++) {
                int r  = wm * 64 + mt * 16 + la;
                int ch = 2 * s + hi;
                ldm_x4(af[mt], sa + r * 128 + ((ch ^ (r & 7)) << 4));
            }
            uint32_t bf[4][2];
#pragma unroll
            for (int nh = 0; nh < 2; nh++) {
                int r  = wn * 32 + nh * 16 + la;
                int ch = 2 * s + hi;
                uint32_t t4[4];
                ldm_x4(t4, sb + r * 128 + ((ch ^ (r & 7)) << 4));
                bf[nh * 2 + 0][0] = t4[0]; bf[nh * 2 + 0][1] = t4[2];
                bf[nh * 2 + 1][0] = t4[1]; bf[nh * 2 + 1][1] = t4[3];
            }
#pragma unroll
            for (int mt = 0; mt < 4; mt++)
#pragma unroll
                for (int nt = 0; nt < 4; nt++)
                    mma16816(acc[mt][nt], af[mt], bf[nt]);
        }
        __syncthreads();
    }

    const int row0 = lane >> 2;
    const int col0 = (lane & 3) * 2;
#pragma unroll
    for (int mt = 0; mt < 4; mt++) {
#pragma unroll
        for (int half = 0; half < 2; half++) {
            int m = m0 + wm * 64 + mt * 16 + row0 + half * 8;
            int w = m >> 6, tt = m & 63;
#pragma unroll
            for (int nt = 0; nt < 4; nt++) {
                int n = n0 + wn * 32 + nt * 8 + col0;
                float v0 = acc[mt][nt][half * 2 + 0];
                float v1 = acc[mt][nt][half * 2 + 1];
                if (mode == 0) {
                    int s = n >> 9, h = (n >> 5) & 15, d = n & 31;
                    float* dst = g_qkv + (((size_t)s * NWIN + w) * 16 + h) * 2048
                               + (size_t)tt * 32 + d;
                    *(float2*)dst = make_float2(v0, v1);
                } else {
                    int b  = w >> 6;
                    int wh = (w >> 3) & 7;
                    int ww = w & 7;
                    int p = tt >> 3, q = tt & 7;
                    int npos = (wh * 8 + p) * 64 + (ww * 8 + q);
                    float2 bi = *(const float2*)(bias + n);
                    float* dst = outp + ((size_t)(b * 4096 + npos)) * 512 + n;
                    *(float2*)dst = make_float2(v0 + bi.x, v1 + bi.y);
                }
            }
        }
    }
}

// ---------------------------------------------------------------------------
// 3) Attention v3 (HMMA): one CTA per (window, head), 4 warps x 16 query rows.
//    S = QK^T via 3 bf16 passes; softmax in registers (shfl row reductions);
//    P split hi/lo in-register; O = PV via 3 bf16 passes with ldmatrix.trans V.
// ---------------------------------------------------------------------------
#define KVSTRIDE 40   // bf16 elems per row (80B) -> conflict-free ldmatrix

__global__ __launch_bounds__(128) void attn_kernel() {
    __shared__ __nv_bfloat16 Khi[64 * KVSTRIDE], Klo[64 * KVSTRIDE];
    __shared__ __nv_bfloat16 Vhi[64 * KVSTRIDE], Vlo[64 * KVSTRIDE];
    const int tid = threadIdx.x;
    const int w = blockIdx.x >> 4;
    const int h = blockIdx.x & 15;
    const size_t base = ((size_t)w * 16 + h) * 2048;
    const float* qb = g_qkv + base;
    const float* kb = g_qkv + (size_t)MTOT * 512 + base;
    const float* vb = g_qkv + (size_t)2 * MTOT * 512 + base;

    // ---- stage K,V as bf16 hi/lo ----
#pragma unroll
    for (int v = 0; v < 4; v++) {
        int fi = tid + v * 128;                 // [0,512): float4 index
        int row = fi >> 3, d0 = (fi & 7) * 4;
        float4 kv = *(const float4*)(kb + row * 32 + d0);
        float4 vv = *(const float4*)(vb + row * 32 + d0);
        __nv_bfloat16 kh0 = __float2bfloat16(kv.x), kh1 = __float2bfloat16(kv.y);
        __nv_bfloat16 kh2 = __float2bfloat16(kv.z), kh3 = __float2bfloat16(kv.w);
        __nv_bfloat16 vh0 = __float2bfloat16(vv.x), vh1 = __float2bfloat16(vv.y);
        __nv_bfloat16 vh2 = __float2bfloat16(vv.z), vh3 = __float2bfloat16(vv.w);
        int so = row * KVSTRIDE + d0;
        *(uint2*)(Khi + so) = make_uint2(packbf(kh0, kh1), packbf(kh2, kh3));
        *(uint2*)(Vhi + so) = make_uint2(packbf(vh0, vh1), packbf(vh2, vh3));
        *(uint2*)(Klo + so) = make_uint2(
            packbf(__float2bfloat16(kv.x - __bfloat162float(kh0)),
                   __float2bfloat16(kv.y - __bfloat162float(kh1))),
            packbf(__float2bfloat16(kv.z - __bfloat162float(kh2)),
                   __float2bfloat16(kv.w - __bfloat162float(kh3))));
        *(uint2*)(Vlo + so) = make_uint2(
            packbf(__float2bfloat16(vv.x - __bfloat162float(vh0)),
                   __float2bfloat16(vv.y - __bfloat162float(vh1))),
            packbf(__float2bfloat16(vv.z - __bfloat162float(vh2)),
                   __float2bfloat16(vv.w - __bfloat162float(vh3))));
    }
    __syncthreads();

    const int lane = tid & 31, wq = tid >> 5;
    const int g  = lane >> 2;            // row within 8
    const int t2 = (lane & 3) * 2;       // col pair
    const uint32_t aKhi = smem_u32(Khi), aKlo = smem_u32(Klo);
    const uint32_t aVhi = smem_u32(Vhi), aVlo = smem_u32(Vlo);

    // ---- Q fragments (from gmem fp32, split hi/lo) ----
    uint32_t qhi[8], qlo[8];
#pragma unroll
    for (int kt = 0; kt < 2; kt++)
#pragma unroll
        for (int pos = 0; pos < 4; pos++) {
            int row = wq * 16 + g + (pos & 1) * 8;
            int col = kt * 16 + t2 + (pos >> 1) * 8;
            float2 qv = *(const float2*)(qb + row * 32 + col);
            __nv_bfloat16 h0 = __float2bfloat16(qv.x), h1 = __float2bfloat16(qv.y);
            qhi[kt * 4 + pos] = packbf(h0, h1);
            qlo[kt * 4 + pos] = packbf(__float2bfloat16(qv.x - __bfloat162float(h0)),
                                       __float2bfloat16(qv.y - __bfloat162float(h1)));
        }

    // ---- S = Q K^T : 3 passes ----
    float sc[8][4];
#pragma unroll
    for (int j = 0; j < 8; j++)
#pragma unroll
        for (int i = 0; i < 4; i++) sc[j][i] = 0.f;

#pragma unroll
    for (int pass = 0; pass < 3; pass++) {
        uint32_t kbase = (pass == 2) ? aKlo : aKhi;
        const uint32_t* qa = (pass == 1) ? qlo : qhi;
#pragma unroll
        for (int kt = 0; kt < 2; kt++) {
#pragma unroll
            for (int nb = 0; nb < 4; nb++) {
                uint32_t t4[4];
                ldm_x4(t4, kbase + (nb * 16 + (lane & 15)) * (KVSTRIDE * 2)
                             + (kt * 2 + (lane >> 4)) * 16);
                uint32_t b0[2] = {t4[0], t4[2]}, b1[2] = {t4[1], t4[3]};
                mma16816(sc[nb * 2 + 0], qa + kt * 4, b0);
                mma16816(sc[nb * 2 + 1], qa + kt * 4, b1);
            }
        }
    }

    // ---- softmax (rows g and g+8; reduce over 4 lanes sharing g) ----
    const float scale = 0.17677669529663687f;
    float m0 = -1e30f, m1 = -1e30f;
#pragma unroll
    for (int j = 0; j < 8; j++) {
#pragma unroll
        for (int i = 0; i < 4; i++) sc[j][i] *= scale;
        m0 = fmaxf(m0, fmaxf(sc[j][0], sc[j][1]));
        m1 = fmaxf(m1, fmaxf(sc[j][2], sc[j][3]));
    }
#pragma unroll
    for (int o = 1; o < 4; o <<= 1) {
        m0 = fmaxf(m0, __shfl_xor_sync(0xffffffffu, m0, o));
        m1 = fmaxf(m1, __shfl_xor_sync(0xffffffffu, m1, o));
    }
    float s0 = 0.f, s1 = 0.f;
#pragma unroll
    for (int j = 0; j < 8; j++) {
        sc[j][0] = __expf(sc[j][0] - m0);
        sc[j][1] = __expf(sc[j][1] - m0);
        sc[j][2] = __expf(sc[j][2] - m1);
        sc[j][3] = __expf(sc[j][3] - m1);
        s0 += sc[j][0] + sc[j][1];
        s1 += sc[j][2] + sc[j][3];
    }
#pragma unroll
    for (int o = 1; o < 4; o <<= 1) {
        s0 += __shfl_xor_sync(0xffffffffu, s0, o);
        s1 += __shfl_xor_sync(0xffffffffu, s1, o);
    }

    // ---- P fragments, hi/lo (in-register C->A permute) ----
    uint32_t phi[16], plo[16];
#pragma unroll
    for (int kt = 0; kt < 4; kt++) {
#pragma unroll
        for (int pos = 0; pos < 4; pos++) {
            int j = 2 * kt + (pos >> 1);
            float a = sc[j][(pos & 1) * 2 + 0];
            float b = sc[j][(pos & 1) * 2 + 1];
            __nv_bfloat16 h0 = __float2bfloat16(a), h1 = __float2bfloat16(b);
            phi[kt * 4 + pos] = packbf(h0, h1);
            plo[kt * 4 + pos] = packbf(__float2bfloat16(a - __bfloat162float(h0)),
                                       __float2bfloat16(b - __bfloat162float(h1)));
        }
    }

    // ---- O = P V : 3 passes, V via ldmatrix.trans ----
    float oc[4][4];
#pragma unroll
    for (int nb = 0; nb < 4; nb++)
#pragma unroll
        for (int i = 0; i < 4; i++) oc[nb][i] = 0.f;

#pragma unroll
    for (int pass = 0; pass < 3; pass++) {
        uint32_t vbase = (pass == 1) ? aVlo : aVhi;
        const uint32_t* pa = (pass == 2) ? plo : phi;
#pragma unroll
        for (int kt = 0; kt < 4; kt++) {
#pragma unroll
            for (int dh = 0; dh < 2; dh++) {
                uint32_t t4[4];
                ldm_x4_t(t4, vbase
                    + (kt * 16 + ((lane >> 3) & 1) * 8 + (lane & 7)) * (KVSTRIDE * 2)
                    + (dh * 16 + ((lane >> 4) & 1) * 8) * 2);
                uint32_t b0[2] = {t4[0], t4[1]}, b1[2] = {t4[2], t4[3]};
                mma16816(oc[dh * 2 + 0], pa + kt * 4, b0);
                mma16816(oc[dh * 2 + 1], pa + kt * 4, b1);
            }
        }
    }

    // ---- normalize + emit bf16 hi/lo for proj GEMM ----
    const float i0 = 1.f / s0, i1 = 1.f / s1;
#pragma unroll
    for (int nb = 0; nb < 4; nb++) {
#pragma unroll
        for (int half = 0; half < 2; half++) {
            int row = w * 64 + wq * 16 + g + half * 8;
            int col = h * 32 + nb * 8 + t2;
            float inv = half ? i1 : i0;
            float a = oc[nb][half * 2 + 0] * inv;
            float b = oc[nb][half * 2 + 1] * inv;
            __nv_bfloat16 h0 = __float2bfloat16(a), h1 = __float2bfloat16(b);
            *(uint32_t*)(g_xo_hi + (size_t)row * 512 + col) = packbf(h0, h1);
            *(uint32_t*)(g_xo_lo + (size_t)row * 512 + col) =
                packbf(__float2bfloat16(a - __bfloat162float(h0)),
                       __float2bfloat16(b - __bfloat162float(h1)));
        }
    }
}

// ---------------------------------------------------------------------------
extern "C" void kernel_launch(void* const* d_in, const int* in_sizes, int n_in,
                              void* d_out, int out_size) {
    const float* x      = (const float*)d_in[0];
    const float* w_qkv  = (const float*)d_in[1];
    const float* w_proj = (const float*)d_in[2];
    const float* b_proj = (const float*)d_in[3];
    float* out = (float*)d_out;

    cudaFuncSetAttribute(gemm3_kernel, cudaFuncAttributeMaxDynamicSharedMemorySize, GSMEM);

    gather_split_kernel<<<16384, 256>>>(x);
    wsplit_kernel<<<4096, 256>>>(w_qkv, w_proj);
    gemm3_kernel<<<dim3(512, 12), 256, GSMEM>>>(nullptr, nullptr, 0);  // QKV
    attn_kernel<<<16384, 128>>>();                                     // HMMA attention
    gemm3_kernel<<<dim3(512, 4), 256, GSMEM>>>(b_proj, out, 1);        // proj
}